// round 4
// baseline (speedup 1.0000x reference)
#include <cuda_runtime.h>
#include <math.h>

#define NB 2
#define NA 512
#define NCGc 64
#define NF 128
#define NF3 384
#define NRBF 20
#define NCONV 3
#define NE 32768
#define BN 1024
#define CUT 5.0f
#define FPI 3.14159265358979323846f
#define WTP 1024
#define WTD 10.0f
#define WSP 4096
#define HN 16384   // NB*NCGc*NF
#define ACH 8      // atom chunks in contract

__device__ float g_h[BN*NF];
__device__ float g_v[BN*NF3];
__device__ float g_dh[BN*NF];
__device__ float g_dv[BN*NF3];
__device__ float g_t1[BN*NF];
__device__ float g_phi[BN*NF3];
__device__ float g_uv[BN*NF3];
__device__ float g_vv[BN*NF3];
__device__ float g_cat[BN*2*NF];
__device__ float g_a[BN*NF3];
__device__ float g_de[NE];
__device__ float g_ue[NE*3];
__device__ float g_dp[NB*NCGc*NA];
__device__ float g_up[NB*NCGc*NA*3];
__device__ float g_wtab[NCONV*WTP*NF3];   // w_c(d) table, d in [0,10]
__device__ float g_wstab[NCONV*WSP*NF3];  // w_s(d)*env(d) table, d in [0,5]

__global__ void k_init(const float* __restrict__ h, const float* __restrict__ Hin,
                       float* __restrict__ out) {
    int i = blockIdx.x*blockDim.x + threadIdx.x;
    if (i < BN*NF3) { g_v[i] = 0.f; g_dv[i] = 0.f; }
    if (i < BN*NF)  { g_h[i] = h[i]; g_dh[i] = 0.f; }
    if (i < HN)     out[i] = Hin[i];
    if (i < HN*3)   out[HN + i] = 0.f;
}

__global__ void k_edge_geom(const int* __restrict__ nbr, const float* __restrict__ xyz) {
    int e = blockIdx.x*blockDim.x + threadIdx.x;
    if (e >= NE) return;
    int b = nbr[3*e], i = nbr[3*e+1], j = nbr[3*e+2];
    float rx = xyz[(b*NA+i)*3+0] - xyz[(b*NA+j)*3+0];
    float ry = xyz[(b*NA+i)*3+1] - xyz[(b*NA+j)*3+1];
    float rz = xyz[(b*NA+i)*3+2] - xyz[(b*NA+j)*3+2];
    float d = sqrtf(rx*rx + ry*ry + rz*rz);
    g_de[e] = d;
    float inv = 1.f/d;
    g_ue[3*e+0] = rx*inv; g_ue[3*e+1] = ry*inv; g_ue[3*e+2] = rz*inv;
}

__global__ void k_pair_geom(const float* __restrict__ xyz, const float* __restrict__ cg) {
    int p = blockIdx.x*blockDim.x + threadIdx.x;
    if (p >= NB*NCGc*NA) return;
    int a = p % NA; int bc = p / NA; int c = bc % NCGc; int b = bc / NCGc;
    float rx = xyz[(b*NA+a)*3+0] - cg[(b*NCGc+c)*3+0];
    float ry = xyz[(b*NA+a)*3+1] - cg[(b*NCGc+c)*3+1];
    float rz = xyz[(b*NA+a)*3+2] - cg[(b*NCGc+c)*3+2];
    float d = sqrtf(rx*rx + ry*ry + rz*rz);
    g_dp[p] = d;
    float inv = 1.f/d;
    g_up[3*p+0] = rx*inv; g_up[3*p+1] = ry*inv; g_up[3*p+2] = rz*inv;
}

// wtab[t][p][m] = sum_g exp(-(d_p - off_g)^2) * Wf[t][g][m] + bf[t][m]
__global__ void k_build_wtab(const float* __restrict__ Wf, const float* __restrict__ bf) {
    int t  = blockIdx.z;
    int m0 = blockIdx.y*16;
    int p  = blockIdx.x*128 + threadIdx.x;
    __shared__ float Ws[NF][16];
    const float* Wt = Wf + t*NF*NF3;
    for (int i = threadIdx.x; i < NF*16; i += 128) {
        int g = i >> 4, m = i & 15;
        Ws[g][m] = Wt[g*NF3 + m0 + m];
    }
    __syncthreads();
    float d = p * (WTD/(float)(WTP-1));
    float acc[16];
    #pragma unroll
    for (int m = 0; m < 16; m++) acc[m] = 0.f;
    for (int g = 0; g < NF; g++) {
        float dd = d - g*(CUT/127.0f);
        float ev = __expf(-dd*dd);
        #pragma unroll
        for (int m = 0; m < 16; m++) acc[m] += ev*Ws[g][m];
    }
    float* op = g_wtab + (size_t)(t*WTP + p)*NF3 + m0;
    #pragma unroll
    for (int m = 0; m < 16; m++) op[m] = acc[m] + bf[t*NF3 + m0 + m];
}

// wstab[t][p][m] = (sum_n rbf_n(d_p)*We[t][n][m] + be[t][m]) * env(d_p)
__global__ void k_build_wstab(const float* __restrict__ We, const float* __restrict__ be) {
    int t  = blockIdx.z;
    int m0 = blockIdx.y*16;
    int p  = blockIdx.x*128 + threadIdx.x;
    __shared__ float Ws[NRBF][16];
    const float* Wt = We + t*NRBF*NF3;
    for (int i = threadIdx.x; i < NRBF*16; i += 128) {
        int n = i >> 4, m = i & 15;
        Ws[n][m] = Wt[n*NF3 + m0 + m];
    }
    __syncthreads();
    float d = p * (CUT/(float)(WSP-1));
    float de = fmaxf(d, 1e-6f);
    float env = 0.5f*(__cosf(FPI*d/CUT) + 1.f);
    float acc[16];
    #pragma unroll
    for (int m = 0; m < 16; m++) acc[m] = 0.f;
    #pragma unroll
    for (int n = 0; n < NRBF; n++) {
        float r = __sinf((n+1)*(FPI/CUT)*de) / de;
        #pragma unroll
        for (int m = 0; m < 16; m++) acc[m] += r*Ws[n][m];
    }
    float* op = g_wstab + (size_t)(t*WSP + p)*NF3 + m0;
    #pragma unroll
    for (int m = 0; m < 16; m++) op[m] = (acc[m] + be[t*NF3 + m0 + m]) * env;
}

// ---- 8x8-micro fp32 GEMM: BM=64, BN=128, BK=16, 128 threads --------------
// C[M x Nn] = act(A@W + b); A strided (lar,lac), C strided (lcr,lcc).
__device__ __forceinline__ void gemm8_body(
        const float* __restrict__ A, int lar, int lac,
        const float* __restrict__ W, const float* __restrict__ bias,
        float* __restrict__ C, int lcr, int lcc,
        int K, int Nn, int act, int bm, int bn) {
    __shared__ float As[16][72];
    __shared__ float Ws[16][128];
    int tid = threadIdx.x;
    int tr = tid >> 4;   // 0..7  -> rows tr*8..tr*8+7
    int tc = tid & 15;   // 0..15 -> cols tc*8..tc*8+7
    float acc[8][8];
    #pragma unroll
    for (int i = 0; i < 8; i++)
        #pragma unroll
        for (int j = 0; j < 8; j++) acc[i][j] = 0.f;
    for (int k0 = 0; k0 < K; k0 += 16) {
        #pragma unroll
        for (int i = tid; i < 64*16; i += 128) {
            int kk = i & 15, r = i >> 4;
            As[kk][r] = A[(size_t)(bm+r)*lar + (size_t)(k0+kk)*lac];
        }
        #pragma unroll
        for (int i = tid; i < 16*128; i += 128) {
            int kk = i >> 7, c = i & 127;
            Ws[kk][c] = W[(size_t)(k0+kk)*Nn + bn + c];
        }
        __syncthreads();
        #pragma unroll
        for (int kk = 0; kk < 16; kk++) {
            float4 a0 = *(const float4*)&As[kk][tr*8];
            float4 a1 = *(const float4*)&As[kk][tr*8+4];
            float4 b0 = *(const float4*)&Ws[kk][tc*8];
            float4 b1 = *(const float4*)&Ws[kk][tc*8+4];
            float av[8] = {a0.x,a0.y,a0.z,a0.w,a1.x,a1.y,a1.z,a1.w};
            float bv[8] = {b0.x,b0.y,b0.z,b0.w,b1.x,b1.y,b1.z,b1.w};
            #pragma unroll
            for (int i = 0; i < 8; i++)
                #pragma unroll
                for (int j = 0; j < 8; j++) acc[i][j] += av[i]*bv[j];
        }
        __syncthreads();
    }
    #pragma unroll
    for (int i = 0; i < 8; i++) {
        int r = bm + tr*8 + i;
        #pragma unroll
        for (int j = 0; j < 8; j++) {
            int c = bn + tc*8 + j;
            float v = acc[i][j] + (bias ? bias[c] : 0.f);
            if (act) v = v / (1.f + __expf(-v));
            C[(size_t)r*lcr + (size_t)c*lcc] = v;
        }
    }
}

__global__ void k_gemm8(const float* __restrict__ A, int lar, int lac,
                        const float* __restrict__ W, const float* __restrict__ bias,
                        float* __restrict__ C, int lcr, int lcc,
                        int K, int Nn, int act) {
    gemm8_body(A, lar, lac, W, bias, C, lcr, lcc, K, Nn, act,
               blockIdx.y*64, blockIdx.x*128);
}

// batched uv/vv: blockIdx.x = which (0:U,1:V), y = M-tile, z = component e
__global__ void k_gemm_uv8(const float* __restrict__ U, const float* __restrict__ V) {
    int e = blockIdx.z;
    int which = blockIdx.x;
    const float* A = g_v + e;
    const float* W = which ? V : U;
    float* C = (which ? g_vv : g_uv) + e;
    gemm8_body(A, NF3, 3, W, nullptr, C, NF3, 3, NF, NF, 0, blockIdx.y*64, 0);
}

// edge messages via wstab lerp; 2 edges per 256-thread block
__global__ void k_edge(const int* __restrict__ nbr, const float* __restrict__ wst) {
    int e = blockIdx.x*2 + (threadIdx.x >> 7);
    int f = threadIdx.x & 127;
    float d = g_de[e];
    if (d >= CUT) return;
    float x = fminf(d * ((float)(WSP-1)/CUT), (float)(WSP-1));
    int p0 = min((int)x, WSP-2);
    float fr = x - (float)p0;
    const float* r0 = wst + (size_t)p0*NF3;
    const float* r1 = r0 + NF3;
    float ws0 = r0[f]      + fr*(r1[f]      - r0[f]);
    float ws1 = r0[NF+f]   + fr*(r1[NF+f]   - r0[NF+f]);
    float ws2 = r0[2*NF+f] + fr*(r1[2*NF+f] - r0[2*NF+f]);
    int b = nbr[3*e], i = nbr[3*e+1], j = nbr[3*e+2];
    int pi = b*NA + i, pj = b*NA + j;
    float i0 = ws0*g_phi[pj*NF3 + f];
    float i1 = ws1*g_phi[pj*NF3 + NF + f];
    float i2 = ws2*g_phi[pj*NF3 + 2*NF + f];
    atomicAdd(&g_dh[pi*NF + f], i1);
    float ux = g_ue[3*e], uy = g_ue[3*e+1], uz = g_ue[3*e+2];
    int vb = pj*NF3 + f*3, ob = pi*NF3 + f*3;
    atomicAdd(&g_dv[ob+0], i2*ux + i0*g_v[vb+0]);
    atomicAdd(&g_dv[ob+1], i2*uy + i0*g_v[vb+1]);
    atomicAdd(&g_dv[ob+2], i2*uz + i0*g_v[vb+2]);
}

__global__ void k_apply_msg() {
    int i = blockIdx.x*blockDim.x + threadIdx.x;
    if (i >= BN*NF3) return;
    g_v[i] += 0.5f*g_dv[i]; g_dv[i] = 0.f;
    if (i < BN*NF) { g_h[i] += 0.5f*g_dh[i]; g_dh[i] = 0.f; }
}

__global__ void k_cat() {
    int i = blockIdx.x*blockDim.x + threadIdx.x;
    if (i >= BN*NF) return;
    int n = i >> 7, g = i & 127;
    g_cat[n*2*NF + g] = g_h[i];
    float x = g_vv[n*NF3 + g*3+0];
    float y = g_vv[n*NF3 + g*3+1];
    float z = g_vv[n*NF3 + g*3+2];
    g_cat[n*2*NF + NF + g] = sqrtf(x*x + y*y + z*z + 1e-15f);
}

__global__ void k_apply_upd() {
    int i = blockIdx.x*blockDim.x + threadIdx.x;
    if (i >= BN*NF) return;
    int n = i >> 7, g = i & 127;
    float u0 = g_uv[n*NF3+g*3+0], u1 = g_uv[n*NF3+g*3+1], u2 = g_uv[n*NF3+g*3+2];
    float w0 = g_vv[n*NF3+g*3+0], w1 = g_vv[n*NF3+g*3+1], w2 = g_vv[n*NF3+g*3+2];
    float dot = u0*w0 + u1*w1 + u2*w2;
    float a0 = g_a[n*NF3 + g];
    float a1 = g_a[n*NF3 + NF + g];
    float a2 = g_a[n*NF3 + 2*NF + g];
    g_h[i] += 0.5f*(dot*a1 + a2);
    g_v[n*NF3+g*3+0] += 0.5f*a0*u0;
    g_v[n*NF3+g*3+1] += 0.5f*a0*u1;
    g_v[n*NF3+g*3+2] += 0.5f*a0*u2;
}

// fused w_c-table lerp * phi_c, assign-weighted reduction, 8-way atom split.
__global__ void k_contract(const float* __restrict__ assign,
                           const float* __restrict__ wt, float* __restrict__ out) {
    int c = blockIdx.x, b = blockIdx.y, f = threadIdx.x;
    int a0 = blockIdx.z * (NA/ACH);
    float accH = 0.f, aV0 = 0.f, aV1 = 0.f, aV2 = 0.f;
    int pc = (b*NCGc + c)*NA;
    #pragma unroll 2
    for (int a = a0; a < a0 + NA/ACH; a++) {
        int pa = b*NA + a;
        float s = __ldg(&assign[pa*NCGc + c]);
        float d = g_dp[pc + a];
        float x = fminf(d * ((WTP-1)/WTD), (float)(WTP-1));
        int p0 = min((int)x, WTP-2);
        float fr = x - (float)p0;
        const float* r0 = wt + (size_t)p0*NF3 + 3*f;
        float w0 = r0[0] + fr*(r0[NF3+0] - r0[0]);
        float w1 = r0[1] + fr*(r0[NF3+1] - r0[1]);
        float w2 = r0[2] + fr*(r0[NF3+2] - r0[2]);
        const float* ph = g_phi + (size_t)pa*NF3 + 3*f;
        const float* vv = g_v   + (size_t)pa*NF3 + 3*f;
        float fw0 = w0*ph[0], fw1 = w1*ph[1], fw2 = w2*ph[2];
        float ux = g_up[(pc+a)*3+0], uy = g_up[(pc+a)*3+1], uz = g_up[(pc+a)*3+2];
        accH += s*fw1;
        aV0  += s*(fw2*ux + fw0*vv[0]);
        aV1  += s*(fw2*uy + fw0*vv[1]);
        aV2  += s*(fw2*uz + fw0*vv[2]);
    }
    int hi = (b*NCGc + c)*NF + f;
    atomicAdd(&out[hi], accH);
    int vo = HN + hi*3;
    atomicAdd(&out[vo+0], aV0);
    atomicAdd(&out[vo+1], aV1);
    atomicAdd(&out[vo+2], aV2);
}

static inline float* sym(const void* s) {
    void* p = nullptr;
    cudaGetSymbolAddress(&p, s);
    return (float*)p;
}

extern "C" void kernel_launch(void* const* d_in, const int* in_sizes, int n_in,
                              void* d_out, int out_size) {
    const float* h      = (const float*)d_in[0];
    const float* Hin    = (const float*)d_in[1];
    const float* xyz    = (const float*)d_in[2];
    const float* cgxyz  = (const float*)d_in[3];
    const float* assign = (const float*)d_in[4];
    const int*   nbr    = (const int*)d_in[6];
    const float* mW1 = (const float*)d_in[7];
    const float* mb1 = (const float*)d_in[8];
    const float* mW2 = (const float*)d_in[9];
    const float* mb2 = (const float*)d_in[10];
    const float* mWe = (const float*)d_in[11];
    const float* mbe = (const float*)d_in[12];
    const float* uU  = (const float*)d_in[13];
    const float* uV  = (const float*)d_in[14];
    const float* uW1 = (const float*)d_in[15];
    const float* ub1 = (const float*)d_in[16];
    const float* uW2 = (const float*)d_in[17];
    const float* ub2 = (const float*)d_in[18];
    const float* cWf = (const float*)d_in[19];
    const float* cbf = (const float*)d_in[20];
    const float* cW1 = (const float*)d_in[21];
    const float* cb1 = (const float*)d_in[22];
    const float* cW2 = (const float*)d_in[23];
    const float* cb2 = (const float*)d_in[24];
    float* out = (float*)d_out;

    float *ph  = sym(g_h),  *pt1 = sym(g_t1), *pphi = sym(g_phi);
    float *pct = sym(g_cat), *pa = sym(g_a);
    float *pwt = sym(g_wtab), *pws = sym(g_wstab);

    k_init<<<1536, 256>>>(h, Hin, out);
    k_edge_geom<<<NE/256, 256>>>(nbr, xyz);
    k_pair_geom<<<(NB*NCGc*NA)/256, 256>>>(xyz, cgxyz);
    k_build_wtab<<<dim3(WTP/128, NF3/16, NCONV), 128>>>(cWf, cbf);
    k_build_wstab<<<dim3(WSP/128, NF3/16, NCONV), 128>>>(mWe, mbe);

    for (int t = 0; t < NCONV; t++) {
        // message phase
        k_gemm8<<<dim3(1,16),128>>>(ph,NF,1, mW1+t*NF*NF, mb1+t*NF, pt1,NF,1, NF,NF,1);
        k_gemm8<<<dim3(3,16),128>>>(pt1,NF,1, mW2+t*NF*NF3, mb2+t*NF3, pphi,NF3,1, NF,NF3,0);
        k_edge<<<NE/2,256>>>(nbr, pws + (size_t)t*WSP*NF3);
        k_apply_msg<<<1536,256>>>();
        // update phase
        k_gemm_uv8<<<dim3(2,16,3),128>>>(uU+t*NF*NF, uV+t*NF*NF);
        k_cat<<<512,256>>>();
        k_gemm8<<<dim3(1,16),128>>>(pct,2*NF,1, uW1+t*2*NF*NF, ub1+t*NF, pt1,NF,1, 2*NF,NF,1);
        k_gemm8<<<dim3(3,16),128>>>(pt1,NF,1, uW2+t*NF*NF3, ub2+t*NF3, pa,NF3,1, NF,NF3,0);
        k_apply_upd<<<512,256>>>();
        // contraction phase
        k_gemm8<<<dim3(1,16),128>>>(ph,NF,1, cW1+t*NF*NF, cb1+t*NF, pt1,NF,1, NF,NF,1);
        k_gemm8<<<dim3(3,16),128>>>(pt1,NF,1, cW2+t*NF*NF3, cb2+t*NF3, pphi,NF3,1, NF,NF3,0);
        k_contract<<<dim3(NCGc,NB,ACH),128>>>(assign, pwt + (size_t)t*WTP*NF3, out);
    }
}

// round 5
// speedup vs baseline: 2.1289x; 2.1289x over previous
#include <cuda_runtime.h>
#include <math.h>

#define NB 2
#define NA 512
#define NCGc 64
#define NF 128
#define NF3 384
#define NRBF 20
#define NCONV 3
#define NE 32768
#define BN 1024
#define CUT 5.0f
#define FPI 3.14159265358979323846f
#define WTP 1024
#define WTD 10.0f
#define WSP 4096
#define HN 16384   // NB*NCGc*NF
#define ACH 8      // atom chunks in contract

__device__ float g_h[BN*NF];
__device__ float g_v[BN*NF3];
__device__ float g_dh[BN*NF];
__device__ float g_dv[BN*NF3];
__device__ float g_phi[BN*NF3];
__device__ float g_uv[BN*NF3];
__device__ float g_vv[BN*NF3];
__device__ float g_cat[BN*2*NF];
__device__ float g_a[BN*NF3];
__device__ float g_de[NE];
__device__ float g_ue[NE*3];
__device__ float g_dp[NB*NCGc*NA];
__device__ float g_up[NB*NCGc*NA*3];
__device__ float g_wtab[NCONV*WTP*NF3];   // w_c(d) table, d in [0,10]
__device__ float g_wstab[NCONV*WSP*NF3];  // w_s(d)*env(d) table, d in [0,5]

__global__ void k_init(const float* __restrict__ h, const float* __restrict__ Hin,
                       float* __restrict__ out) {
    int i = blockIdx.x*blockDim.x + threadIdx.x;
    if (i < BN*NF3) { g_v[i] = 0.f; g_dv[i] = 0.f; }
    if (i < BN*NF)  { g_h[i] = h[i]; g_dh[i] = 0.f; }
    if (i < HN)     out[i] = Hin[i];
    if (i < HN*3)   out[HN + i] = 0.f;
}

__global__ void k_edge_geom(const int* __restrict__ nbr, const float* __restrict__ xyz) {
    int e = blockIdx.x*blockDim.x + threadIdx.x;
    if (e >= NE) return;
    int b = nbr[3*e], i = nbr[3*e+1], j = nbr[3*e+2];
    float rx = xyz[(b*NA+i)*3+0] - xyz[(b*NA+j)*3+0];
    float ry = xyz[(b*NA+i)*3+1] - xyz[(b*NA+j)*3+1];
    float rz = xyz[(b*NA+i)*3+2] - xyz[(b*NA+j)*3+2];
    float d = sqrtf(rx*rx + ry*ry + rz*rz);
    g_de[e] = d;
    float inv = 1.f/d;
    g_ue[3*e+0] = rx*inv; g_ue[3*e+1] = ry*inv; g_ue[3*e+2] = rz*inv;
}

__global__ void k_pair_geom(const float* __restrict__ xyz, const float* __restrict__ cg) {
    int p = blockIdx.x*blockDim.x + threadIdx.x;
    if (p >= NB*NCGc*NA) return;
    int a = p % NA; int bc = p / NA; int c = bc % NCGc; int b = bc / NCGc;
    float rx = xyz[(b*NA+a)*3+0] - cg[(b*NCGc+c)*3+0];
    float ry = xyz[(b*NA+a)*3+1] - cg[(b*NCGc+c)*3+1];
    float rz = xyz[(b*NA+a)*3+2] - cg[(b*NCGc+c)*3+2];
    float d = sqrtf(rx*rx + ry*ry + rz*rz);
    g_dp[p] = d;
    float inv = 1.f/d;
    g_up[3*p+0] = rx*inv; g_up[3*p+1] = ry*inv; g_up[3*p+2] = rz*inv;
}

__global__ void k_build_wtab(const float* __restrict__ Wf, const float* __restrict__ bf) {
    int t  = blockIdx.z;
    int m0 = blockIdx.y*16;
    int p  = blockIdx.x*128 + threadIdx.x;
    __shared__ float Ws[NF][16];
    const float* Wt = Wf + t*NF*NF3;
    for (int i = threadIdx.x; i < NF*16; i += 128) {
        int g = i >> 4, m = i & 15;
        Ws[g][m] = Wt[g*NF3 + m0 + m];
    }
    __syncthreads();
    float d = p * (WTD/(float)(WTP-1));
    float acc[16];
    #pragma unroll
    for (int m = 0; m < 16; m++) acc[m] = 0.f;
    for (int g = 0; g < NF; g++) {
        float dd = d - g*(CUT/127.0f);
        float ev = __expf(-dd*dd);
        #pragma unroll
        for (int m = 0; m < 16; m++) acc[m] += ev*Ws[g][m];
    }
    float* op = g_wtab + (size_t)(t*WTP + p)*NF3 + m0;
    #pragma unroll
    for (int m = 0; m < 16; m++) op[m] = acc[m] + bf[t*NF3 + m0 + m];
}

__global__ void k_build_wstab(const float* __restrict__ We, const float* __restrict__ be) {
    int t  = blockIdx.z;
    int m0 = blockIdx.y*16;
    int p  = blockIdx.x*128 + threadIdx.x;
    __shared__ float Ws[NRBF][16];
    const float* Wt = We + t*NRBF*NF3;
    for (int i = threadIdx.x; i < NRBF*16; i += 128) {
        int n = i >> 4, m = i & 15;
        Ws[n][m] = Wt[n*NF3 + m0 + m];
    }
    __syncthreads();
    float d = p * (CUT/(float)(WSP-1));
    float de = fmaxf(d, 1e-6f);
    float env = 0.5f*(__cosf(FPI*d/CUT) + 1.f);
    float acc[16];
    #pragma unroll
    for (int m = 0; m < 16; m++) acc[m] = 0.f;
    #pragma unroll
    for (int n = 0; n < NRBF; n++) {
        float r = __sinf((n+1)*(FPI/CUT)*de) / de;
        #pragma unroll
        for (int m = 0; m < 16; m++) acc[m] += r*Ws[n][m];
    }
    float* op = g_wstab + (size_t)(t*WSP + p)*NF3 + m0;
    #pragma unroll
    for (int m = 0; m < 16; m++) op[m] = (acc[m] + be[t*NF3 + m0 + m]) * env;
}

// ---- fused MLP: out[M x 384] = silu(A[M x K] @ W1[K x 128] + b1) @ W2[128 x 384] + b2
// Block: 64 rows x 64 out-cols, 256 threads. t1 stays in smem.
// Dynamic smem layout (floats): As[16][65] | W1s[16][128] | t1s[64][129] | W2s[128][64]
#define MLP_SMEM ((16*65 + 16*128 + 64*129 + 128*64) * 4)
__global__ void k_mlp(const float* __restrict__ A, int K,
                      const float* __restrict__ W1, const float* __restrict__ b1,
                      const float* __restrict__ W2, const float* __restrict__ b2,
                      float* __restrict__ C) {
    extern __shared__ float sm[];
    float* As  = sm;                       // [16][65]
    float* W1s = sm + 16*65;               // [16][128]
    float* t1s = W1s + 16*128;             // [64][129]
    float* W2s = t1s + 64*129;             // [128][64]
    int row0 = blockIdx.y*64;
    int col0 = blockIdx.x*64;
    int tid = threadIdx.x;
    int ty = tid >> 4;       // 0..15
    int tx = tid & 15;       // 0..15

    float acc1[4][8];
    #pragma unroll
    for (int i = 0; i < 4; i++)
        #pragma unroll
        for (int j = 0; j < 8; j++) acc1[i][j] = 0.f;

    int nk = K >> 4;
    for (int it = 0; it < nk; it++) {
        int k0 = it*16;
        // A tile 64x16 -> As[kk][r]
        #pragma unroll
        for (int p = 0; p < 4; p++) {
            int idx = tid + p*256;
            int kk = idx & 15, r = idx >> 4;
            As[kk*65 + r] = A[(size_t)(row0+r)*K + k0 + kk];
        }
        // W1 tile 16x128 -> W1s[kk][c]
        #pragma unroll
        for (int p = 0; p < 8; p++) {
            int idx = tid + p*256;
            int kk = idx >> 7, c = idx & 127;
            W1s[kk*128 + c] = W1[(size_t)(k0+kk)*128 + c];
        }
        // prefetch W2 chunk (16 k-rows) into W2s during first 8 iterations
        if (it < 8) {
            #pragma unroll
            for (int p = 0; p < 4; p++) {
                int idx = tid + p*256;
                int kk = it*16 + (idx >> 6), c = idx & 63;
                W2s[kk*64 + c] = W2[(size_t)kk*NF3 + col0 + c];
            }
        }
        __syncthreads();
        #pragma unroll
        for (int kk = 0; kk < 16; kk++) {
            float a[4], w[8];
            #pragma unroll
            for (int i = 0; i < 4; i++) a[i] = As[kk*65 + ty + 16*i];
            #pragma unroll
            for (int j = 0; j < 8; j++) w[j] = W1s[kk*128 + tx + 16*j];
            #pragma unroll
            for (int i = 0; i < 4; i++)
                #pragma unroll
                for (int j = 0; j < 8; j++) acc1[i][j] += a[i]*w[j];
        }
        __syncthreads();
    }
    // silu + store t1 to smem: t1 element (row ty+16i, k-col tx+16j)
    #pragma unroll
    for (int i = 0; i < 4; i++)
        #pragma unroll
        for (int j = 0; j < 8; j++) {
            int c = tx + 16*j;
            float v = acc1[i][j] + b1[c];
            v = v / (1.f + __expf(-v));
            t1s[(ty + 16*i)*129 + c] = v;
        }
    __syncthreads();

    // stage 2: out 64x64 = t1 @ W2slice
    float acc2[4][4];
    #pragma unroll
    for (int i = 0; i < 4; i++)
        #pragma unroll
        for (int j = 0; j < 4; j++) acc2[i][j] = 0.f;
    #pragma unroll 4
    for (int kk = 0; kk < 128; kk++) {
        float a2[4], w2v[4];
        #pragma unroll
        for (int i = 0; i < 4; i++) a2[i] = t1s[(ty + 16*i)*129 + kk];
        #pragma unroll
        for (int j = 0; j < 4; j++) w2v[j] = W2s[kk*64 + tx + 16*j];
        #pragma unroll
        for (int i = 0; i < 4; i++)
            #pragma unroll
            for (int j = 0; j < 4; j++) acc2[i][j] += a2[i]*w2v[j];
    }
    #pragma unroll
    for (int i = 0; i < 4; i++) {
        int r = row0 + ty + 16*i;
        #pragma unroll
        for (int j = 0; j < 4; j++) {
            int c = col0 + tx + 16*j;
            C[(size_t)r*NF3 + c] = acc2[i][j] + b2[c];
        }
    }
}

// batched uv/vv GEMM (R3 config): blockIdx.z = component e, x selects {n-tile, U/V}
__global__ void k_gemm_uv(const float* __restrict__ U, const float* __restrict__ V) {
    __shared__ float As[16][65];
    __shared__ float Ws[16][64];
    int e = blockIdx.z;
    int which = blockIdx.x >> 1;
    int bn = (blockIdx.x & 1)*64;
    int bm = blockIdx.y*64;
    const float* A = g_v + e;
    const float* W = which ? V : U;
    float* C = (which ? g_vv : g_uv) + e;
    int tid = threadIdx.x;
    int tr = tid >> 4, tc = tid & 15;
    float acc[4][4];
    #pragma unroll
    for (int i = 0; i < 4; i++)
        #pragma unroll
        for (int j = 0; j < 4; j++) acc[i][j] = 0.f;
    for (int k0 = 0; k0 < NF; k0 += 16) {
        for (int i = tid; i < 64*16; i += 256) {
            int kk = i & 15, r = i >> 4;
            As[kk][r] = A[(size_t)(bm+r)*NF3 + (size_t)(k0+kk)*3];
        }
        for (int i = tid; i < 16*64; i += 256) {
            int kk = i >> 6, c = i & 63;
            Ws[kk][c] = W[(size_t)(k0+kk)*NF + bn + c];
        }
        __syncthreads();
        #pragma unroll
        for (int kk = 0; kk < 16; kk++) {
            float av[4], bv[4];
            #pragma unroll
            for (int i = 0; i < 4; i++) av[i] = As[kk][tr*4+i];
            #pragma unroll
            for (int j = 0; j < 4; j++) bv[j] = Ws[kk][tc*4+j];
            #pragma unroll
            for (int i = 0; i < 4; i++)
                #pragma unroll
                for (int j = 0; j < 4; j++) acc[i][j] += av[i]*bv[j];
        }
        __syncthreads();
    }
    #pragma unroll
    for (int i = 0; i < 4; i++) {
        int r = bm + tr*4 + i;
        #pragma unroll
        for (int j = 0; j < 4; j++) {
            int c = bn + tc*4 + j;
            C[(size_t)r*NF3 + (size_t)c*3] = acc[i][j];
        }
    }
}

// edge messages via wstab lerp; 2 edges per 256-thread block
__global__ void k_edge(const int* __restrict__ nbr, const float* __restrict__ wst) {
    int e = blockIdx.x*2 + (threadIdx.x >> 7);
    int f = threadIdx.x & 127;
    float d = g_de[e];
    if (d >= CUT) return;
    float x = fminf(d * ((float)(WSP-1)/CUT), (float)(WSP-1));
    int p0 = min((int)x, WSP-2);
    float fr = x - (float)p0;
    const float* r0 = wst + (size_t)p0*NF3;
    const float* r1 = r0 + NF3;
    float ws0 = r0[f]      + fr*(r1[f]      - r0[f]);
    float ws1 = r0[NF+f]   + fr*(r1[NF+f]   - r0[NF+f]);
    float ws2 = r0[2*NF+f] + fr*(r1[2*NF+f] - r0[2*NF+f]);
    int b = nbr[3*e], i = nbr[3*e+1], j = nbr[3*e+2];
    int pi = b*NA + i, pj = b*NA + j;
    float i0 = ws0*g_phi[pj*NF3 + f];
    float i1 = ws1*g_phi[pj*NF3 + NF + f];
    float i2 = ws2*g_phi[pj*NF3 + 2*NF + f];
    atomicAdd(&g_dh[pi*NF + f], i1);
    float ux = g_ue[3*e], uy = g_ue[3*e+1], uz = g_ue[3*e+2];
    int vb = pj*NF3 + f*3, ob = pi*NF3 + f*3;
    atomicAdd(&g_dv[ob+0], i2*ux + i0*g_v[vb+0]);
    atomicAdd(&g_dv[ob+1], i2*uy + i0*g_v[vb+1]);
    atomicAdd(&g_dv[ob+2], i2*uz + i0*g_v[vb+2]);
}

__global__ void k_apply_msg() {
    int i = blockIdx.x*blockDim.x + threadIdx.x;
    if (i >= BN*NF3) return;
    g_v[i] += 0.5f*g_dv[i]; g_dv[i] = 0.f;
    if (i < BN*NF) { g_h[i] += 0.5f*g_dh[i]; g_dh[i] = 0.f; }
}

__global__ void k_cat() {
    int i = blockIdx.x*blockDim.x + threadIdx.x;
    if (i >= BN*NF) return;
    int n = i >> 7, g = i & 127;
    g_cat[n*2*NF + g] = g_h[i];
    float x = g_vv[n*NF3 + g*3+0];
    float y = g_vv[n*NF3 + g*3+1];
    float z = g_vv[n*NF3 + g*3+2];
    g_cat[n*2*NF + NF + g] = sqrtf(x*x + y*y + z*z + 1e-15f);
}

__global__ void k_apply_upd() {
    int i = blockIdx.x*blockDim.x + threadIdx.x;
    if (i >= BN*NF) return;
    int n = i >> 7, g = i & 127;
    float u0 = g_uv[n*NF3+g*3+0], u1 = g_uv[n*NF3+g*3+1], u2 = g_uv[n*NF3+g*3+2];
    float w0 = g_vv[n*NF3+g*3+0], w1 = g_vv[n*NF3+g*3+1], w2 = g_vv[n*NF3+g*3+2];
    float dot = u0*w0 + u1*w1 + u2*w2;
    float a0 = g_a[n*NF3 + g];
    float a1 = g_a[n*NF3 + NF + g];
    float a2 = g_a[n*NF3 + 2*NF + g];
    g_h[i] += 0.5f*(dot*a1 + a2);
    g_v[n*NF3+g*3+0] += 0.5f*a0*u0;
    g_v[n*NF3+g*3+1] += 0.5f*a0*u1;
    g_v[n*NF3+g*3+2] += 0.5f*a0*u2;
}

__global__ void k_contract(const float* __restrict__ assign,
                           const float* __restrict__ wt, float* __restrict__ out) {
    int c = blockIdx.x, b = blockIdx.y, f = threadIdx.x;
    int a0 = blockIdx.z * (NA/ACH);
    float accH = 0.f, aV0 = 0.f, aV1 = 0.f, aV2 = 0.f;
    int pc = (b*NCGc + c)*NA;
    #pragma unroll 2
    for (int a = a0; a < a0 + NA/ACH; a++) {
        int pa = b*NA + a;
        float s = __ldg(&assign[pa*NCGc + c]);
        float d = g_dp[pc + a];
        float x = fminf(d * ((WTP-1)/WTD), (float)(WTP-1));
        int p0 = min((int)x, WTP-2);
        float fr = x - (float)p0;
        const float* r0 = wt + (size_t)p0*NF3 + 3*f;
        float w0 = r0[0] + fr*(r0[NF3+0] - r0[0]);
        float w1 = r0[1] + fr*(r0[NF3+1] - r0[1]);
        float w2 = r0[2] + fr*(r0[NF3+2] - r0[2]);
        const float* ph = g_phi + (size_t)pa*NF3 + 3*f;
        const float* vv = g_v   + (size_t)pa*NF3 + 3*f;
        float fw0 = w0*ph[0], fw1 = w1*ph[1], fw2 = w2*ph[2];
        float ux = g_up[(pc+a)*3+0], uy = g_up[(pc+a)*3+1], uz = g_up[(pc+a)*3+2];
        accH += s*fw1;
        aV0  += s*(fw2*ux + fw0*vv[0]);
        aV1  += s*(fw2*uy + fw0*vv[1]);
        aV2  += s*(fw2*uz + fw0*vv[2]);
    }
    int hi = (b*NCGc + c)*NF + f;
    atomicAdd(&out[hi], accH);
    int vo = HN + hi*3;
    atomicAdd(&out[vo+0], aV0);
    atomicAdd(&out[vo+1], aV1);
    atomicAdd(&out[vo+2], aV2);
}

static inline float* sym(const void* s) {
    void* p = nullptr;
    cudaGetSymbolAddress(&p, s);
    return (float*)p;
}

extern "C" void kernel_launch(void* const* d_in, const int* in_sizes, int n_in,
                              void* d_out, int out_size) {
    const float* h      = (const float*)d_in[0];
    const float* Hin    = (const float*)d_in[1];
    const float* xyz    = (const float*)d_in[2];
    const float* cgxyz  = (const float*)d_in[3];
    const float* assign = (const float*)d_in[4];
    const int*   nbr    = (const int*)d_in[6];
    const float* mW1 = (const float*)d_in[7];
    const float* mb1 = (const float*)d_in[8];
    const float* mW2 = (const float*)d_in[9];
    const float* mb2 = (const float*)d_in[10];
    const float* mWe = (const float*)d_in[11];
    const float* mbe = (const float*)d_in[12];
    const float* uU  = (const float*)d_in[13];
    const float* uV  = (const float*)d_in[14];
    const float* uW1 = (const float*)d_in[15];
    const float* ub1 = (const float*)d_in[16];
    const float* uW2 = (const float*)d_in[17];
    const float* ub2 = (const float*)d_in[18];
    const float* cWf = (const float*)d_in[19];
    const float* cbf = (const float*)d_in[20];
    const float* cW1 = (const float*)d_in[21];
    const float* cb1 = (const float*)d_in[22];
    const float* cW2 = (const float*)d_in[23];
    const float* cb2 = (const float*)d_in[24];
    float* out = (float*)d_out;

    float *ph  = sym(g_h),  *pphi = sym(g_phi);
    float *pct = sym(g_cat), *pa = sym(g_a);
    float *pwt = sym(g_wtab), *pws = sym(g_wstab);

    cudaFuncSetAttribute(k_mlp, cudaFuncAttributeMaxDynamicSharedMemorySize, MLP_SMEM);

    k_init<<<1536, 256>>>(h, Hin, out);
    k_edge_geom<<<NE/256, 256>>>(nbr, xyz);
    k_pair_geom<<<(NB*NCGc*NA)/256, 256>>>(xyz, cgxyz);
    k_build_wtab<<<dim3(WTP/128, NF3/16, NCONV), 128>>>(cWf, cbf);
    k_build_wstab<<<dim3(WSP/128, NF3/16, NCONV), 128>>>(mWe, mbe);

    for (int t = 0; t < NCONV; t++) {
        // message phase: fused MLP -> phi
        k_mlp<<<dim3(6,16),256,MLP_SMEM>>>(ph, NF, mW1+t*NF*NF, mb1+t*NF,
                                           mW2+t*NF*NF3, mb2+t*NF3, pphi);
        k_edge<<<NE/2,256>>>(nbr, pws + (size_t)t*WSP*NF3);
        k_apply_msg<<<1536,256>>>();
        // update phase
        k_gemm_uv<<<dim3(4,16,3),256>>>(uU+t*NF*NF, uV+t*NF*NF);
        k_cat<<<512,256>>>();
        k_mlp<<<dim3(6,16),256,MLP_SMEM>>>(pct, 2*NF, uW1+t*2*NF*NF, ub1+t*NF,
                                           uW2+t*NF*NF3, ub2+t*NF3, pa);
        k_apply_upd<<<512,256>>>();
        // contraction phase: fused MLP -> phi_c, then contract
        k_mlp<<<dim3(6,16),256,MLP_SMEM>>>(ph, NF, cW1+t*NF*NF, cb1+t*NF,
                                           cW2+t*NF*NF3, cb2+t*NF3, pphi);
        k_contract<<<dim3(NCGc,NB,ACH),128>>>(assign, pwt + (size_t)t*WTP*NF3, out);
    }
}